// round 9
// baseline (speedup 1.0000x reference)
#include <cuda_runtime.h>

#define BB 256
#define DD 5120
#define NN 16
#define RR 160
#define JJ 192          // RR + 32 (B/C projections)
#define KSPLIT 80
#define KCH (DD / KSPLIT)   // 64
#define BK 16

// Scratch (device globals — no allocations allowed)
__device__ float g_P[KSPLIT * BB * JJ];   // split-K partials (15.7 MB)
__device__ float g_T[BB * JJ];            // reduced projections
__device__ float g_DT[BB * DD];           // dt (5.2 MB)

__device__ __forceinline__ float ex2f(float v) {
    float r;
    asm("ex2.approx.ftz.f32 %0, %1;" : "=f"(r) : "f"(v));
    return r;
}

typedef unsigned long long ull;

__device__ __forceinline__ ull fma2(ull a, ull b, ull c) {
    ull d;
    asm("fma.rn.f32x2 %0, %1, %2, %3;" : "=l"(d) : "l"(a), "l"(b), "l"(c));
    return d;
}
__device__ __forceinline__ float2 unpk(ull v) {
    float2 r;
    asm("mov.b64 {%0, %1}, %2;" : "=f"(r.x), "=f"(r.y) : "l"(v));
    return r;
}

// ---------------------------------------------------------------------------
// Kernel 1 (v3): split-K GEMM. P[ks] = x[:, k-chunk] @ [W_x_dt | W_BC]
// Tile 128(M) x 64(N), BK=16, double-buffered, 128 threads, micro 8M x 8N.
// 1.5 smem B/FMA; 6 LDS per 32 FFMA2 -> FFMA2-issue bound, not crossbar.
// Grid (2, 3, 80) = 480 blocks.
// ---------------------------------------------------------------------------
__global__ __launch_bounds__(128) void mamba_proj_kernel(
    const float* __restrict__ x, const float* __restrict__ Wx,
    const float* __restrict__ Wbc, const float* __restrict__ h0)
{
    __shared__ float2 As2[2][BK][130];  // [buf][k][m] duplicated, padded
    __shared__ float  Bs[2][BK][64];    // [buf][k][n]
    const int m0 = blockIdx.x * 128;
    const int n0 = blockIdx.y * 64;
    const int k0 = blockIdx.z * KCH;
    const int tid = threadIdx.x;
    const int tx = tid & 7, ty = tid >> 3;    // micro coords: n=tx*8, m=ty*8

    // ---- h0 L2 prefetch: 655360 lines over 480 blocks ----
    {
        const int bid = blockIdx.x + blockIdx.y * 2 + blockIdx.z * 6;  // 0..479
        const size_t total = (size_t)BB * DD * NN;
        size_t base = (size_t)bid * 1366 * 32;
#pragma unroll
        for (int i = 0; i < 11; i++) {
            size_t off = base + ((size_t)(tid + i * 128)) * 32;
            if ((tid + i * 128) < 1366 && off < total)
                asm volatile("prefetch.global.L2 [%0];" :: "l"(h0 + off) : "memory");
        }
    }

    // B loader: thread covers rows bk_ and bk_+8
    const int bk_ = tid >> 4, bn = (tid & 15) << 2;
    const int j = n0 + bn;
    const float* bbase;
    size_t bstride;
    if (j < RR) { bbase = Wx + j;         bstride = RR; }
    else        { bbase = Wbc + (j - RR); bstride = 32; }

    // A loader: thread owns row m = tid, 4 float4s along k
    const float* asrc = &x[(size_t)(m0 + tid) * DD + k0];

    ull acc2[8][4] = {};

    // prologue: chunk 0
    float4 av0 = *(const float4*)(asrc + 0);
    float4 av1 = *(const float4*)(asrc + 4);
    float4 av2 = *(const float4*)(asrc + 8);
    float4 av3 = *(const float4*)(asrc + 12);
    float4 bv0 = *(const float4*)&bbase[(size_t)(k0 + bk_) * bstride];
    float4 bv1 = *(const float4*)&bbase[(size_t)(k0 + bk_ + 8) * bstride];
#pragma unroll
    for (int q = 0; q < 4; q++) {
        const float4 av = q == 0 ? av0 : q == 1 ? av1 : q == 2 ? av2 : av3;
        As2[0][q * 4 + 0][tid] = make_float2(av.x, av.x);
        As2[0][q * 4 + 1][tid] = make_float2(av.y, av.y);
        As2[0][q * 4 + 2][tid] = make_float2(av.z, av.z);
        As2[0][q * 4 + 3][tid] = make_float2(av.w, av.w);
    }
    *(float4*)&Bs[0][bk_][bn] = bv0;
    *(float4*)&Bs[0][bk_ + 8][bn] = bv1;
    __syncthreads();

#pragma unroll
    for (int c = 0; c < KCH / BK; c++) {
        const int cur = c & 1;
        if (c + 1 < KCH / BK) {
            const int kn = k0 + (c + 1) * BK;
            av0 = *(const float4*)(asrc + (c + 1) * BK + 0);
            av1 = *(const float4*)(asrc + (c + 1) * BK + 4);
            av2 = *(const float4*)(asrc + (c + 1) * BK + 8);
            av3 = *(const float4*)(asrc + (c + 1) * BK + 12);
            bv0 = *(const float4*)&bbase[(size_t)(kn + bk_) * bstride];
            bv1 = *(const float4*)&bbase[(size_t)(kn + bk_ + 8) * bstride];
        }
#pragma unroll
        for (int kk = 0; kk < BK; kk++) {
            ulonglong2 b01 = *(const ulonglong2*)&Bs[cur][kk][tx * 8];
            ulonglong2 b23 = *(const ulonglong2*)&Bs[cur][kk][tx * 8 + 4];
#pragma unroll
            for (int mp = 0; mp < 4; mp++) {
                ulonglong2 aq = *(const ulonglong2*)&As2[cur][kk][ty * 8 + mp * 2];
                acc2[mp * 2 + 0][0] = fma2(aq.x, b01.x, acc2[mp * 2 + 0][0]);
                acc2[mp * 2 + 0][1] = fma2(aq.x, b01.y, acc2[mp * 2 + 0][1]);
                acc2[mp * 2 + 0][2] = fma2(aq.x, b23.x, acc2[mp * 2 + 0][2]);
                acc2[mp * 2 + 0][3] = fma2(aq.x, b23.y, acc2[mp * 2 + 0][3]);
                acc2[mp * 2 + 1][0] = fma2(aq.y, b01.x, acc2[mp * 2 + 1][0]);
                acc2[mp * 2 + 1][1] = fma2(aq.y, b01.y, acc2[mp * 2 + 1][1]);
                acc2[mp * 2 + 1][2] = fma2(aq.y, b23.x, acc2[mp * 2 + 1][2]);
                acc2[mp * 2 + 1][3] = fma2(aq.y, b23.y, acc2[mp * 2 + 1][3]);
            }
        }
        if (c + 1 < KCH / BK) {
            const int nxt = cur ^ 1;
            __syncthreads();
#pragma unroll
            for (int q = 0; q < 4; q++) {
                const float4 av = q == 0 ? av0 : q == 1 ? av1 : q == 2 ? av2 : av3;
                As2[nxt][q * 4 + 0][tid] = make_float2(av.x, av.x);
                As2[nxt][q * 4 + 1][tid] = make_float2(av.y, av.y);
                As2[nxt][q * 4 + 2][tid] = make_float2(av.z, av.z);
                As2[nxt][q * 4 + 3][tid] = make_float2(av.w, av.w);
            }
            *(float4*)&Bs[nxt][bk_][bn] = bv0;
            *(float4*)&Bs[nxt][bk_ + 8][bn] = bv1;
            __syncthreads();
        }
    }

    float* dst = &g_P[(size_t)blockIdx.z * (BB * JJ)];
#pragma unroll
    for (int i = 0; i < 8; i++) {
        float2 p0 = unpk(acc2[i][0]);
        float2 p1 = unpk(acc2[i][1]);
        float2 p2 = unpk(acc2[i][2]);
        float2 p3 = unpk(acc2[i][3]);
        float* row = &dst[(size_t)(m0 + ty * 8 + i) * JJ + n0 + tx * 8];
        *(float4*)(row + 0) = make_float4(p0.x, p0.y, p1.x, p1.y);
        *(float4*)(row + 4) = make_float4(p2.x, p2.y, p3.x, p3.y);
    }
}

// ---------------------------------------------------------------------------
// Kernel 1r: reduce split-K partials. One thread per float, grid 192.
// g_P is freshly-written (L2-resident), so this is L2-bound, ~2.5 us.
// ---------------------------------------------------------------------------
__global__ __launch_bounds__(256) void mamba_reduce_kernel()
{
    const int idx = blockIdx.x * 256 + threadIdx.x;
    float s = 0.f;
#pragma unroll 16
    for (int ks = 0; ks < KSPLIT; ks++) s += g_P[ks * (BB * JJ) + idx];
    g_T[idx] = s;
}

// ---------------------------------------------------------------------------
// Kernel 2a: dt GEMM.  z = t @ W_dt + b_dt ; dt = softplus(z) -> g_DT
// (unchanged from R6/R7/R8)
// ---------------------------------------------------------------------------
__global__ __launch_bounds__(256) void mamba_dt_kernel(
    const float* __restrict__ Wdt, const float* __restrict__ bdt)
{
    const int d0 = blockIdx.x * 128;
    const int b0 = blockIdx.y * 32;
    const int tid = threadIdx.x;
    const int tdx = tid & 31;     // d lane (4 consecutive d)
    const int tby = tid >> 5;     // warp id = b group (4 b per warp)

    __shared__ float2 Ts2[32][160];  // t tile, duplicated (41 KB)
    __shared__ float  Ws[16][128];   // W_dt chunk
    __shared__ float  bds[128];

    for (int v = tid; v < 1280; v += 256) {
        int b = v / 40, r4 = (v - b * 40) * 4;
        float4 t4 = *(const float4*)&g_T[(b0 + b) * JJ + r4];
        Ts2[b][r4 + 0] = make_float2(t4.x, t4.x);
        Ts2[b][r4 + 1] = make_float2(t4.y, t4.y);
        Ts2[b][r4 + 2] = make_float2(t4.z, t4.z);
        Ts2[b][r4 + 3] = make_float2(t4.w, t4.w);
    }
    if (tid < 128) bds[tid] = bdt[d0 + tid];

    ull acc2[4][2] = {};
    const int wr = tid >> 4;          // 0..15
    const int wc = (tid & 15) << 3;   // 0..120
    for (int rc = 0; rc < RR; rc += 16) {
        const float* wsrc = &Wdt[(size_t)(rc + wr) * DD + d0 + wc];
        float4 w0 = *(const float4*)wsrc;
        float4 w1 = *(const float4*)(wsrc + 4);
        __syncthreads();
        *(float4*)&Ws[wr][wc] = w0;
        *(float4*)&Ws[wr][wc + 4] = w1;
        __syncthreads();
#pragma unroll
        for (int rr = 0; rr < 16; rr++) {
            ulonglong2 wq = *(const ulonglong2*)&Ws[rr][tdx * 4];
            ull a0 = *(const ull*)&Ts2[tby * 4 + 0][rc + rr];  // bcast LDS.64
            ull a1 = *(const ull*)&Ts2[tby * 4 + 1][rc + rr];
            ull a2 = *(const ull*)&Ts2[tby * 4 + 2][rc + rr];
            ull a3 = *(const ull*)&Ts2[tby * 4 + 3][rc + rr];
            acc2[0][0] = fma2(a0, wq.x, acc2[0][0]);
            acc2[0][1] = fma2(a0, wq.y, acc2[0][1]);
            acc2[1][0] = fma2(a1, wq.x, acc2[1][0]);
            acc2[1][1] = fma2(a1, wq.y, acc2[1][1]);
            acc2[2][0] = fma2(a2, wq.x, acc2[2][0]);
            acc2[2][1] = fma2(a2, wq.y, acc2[2][1]);
            acc2[3][0] = fma2(a3, wq.x, acc2[3][0]);
            acc2[3][1] = fma2(a3, wq.y, acc2[3][1]);
        }
    }

    float4 bdv = *(const float4*)&bds[tdx * 4];
#pragma unroll
    for (int bi = 0; bi < 4; bi++) {
        const int bl = tby * 4 + bi;
        float2 p0 = unpk(acc2[bi][0]);
        float2 p1 = unpk(acc2[bi][1]);
        float z0 = p0.x + bdv.x, z1 = p0.y + bdv.y;
        float z2 = p1.x + bdv.z, z3 = p1.y + bdv.w;
        float4 dtv;
        dtv.x = fmaxf(z0, 0.f) + log1pf(__expf(-fabsf(z0)));
        dtv.y = fmaxf(z1, 0.f) + log1pf(__expf(-fabsf(z1)));
        dtv.z = fmaxf(z2, 0.f) + log1pf(__expf(-fabsf(z2)));
        dtv.w = fmaxf(z3, 0.f) + log1pf(__expf(-fabsf(z3)));
        *(float4*)&g_DT[(size_t)(b0 + bl) * DD + d0 + tdx * 4] = dtv;
    }
}

// ---------------------------------------------------------------------------
// Kernel 2b: h0 stream. d-tile 64 -> grid (80, 16) = 1280 blocks (~5/SM
// resident, ~40 warps) for more loads in flight.
//   y[b,d] = sum_n ex2(A2[d,n]*dt)*h0[b,d,n]*C[b,n] + dt*x*SBC[b] + x
// ---------------------------------------------------------------------------
__global__ __launch_bounds__(256) void mamba_scan_kernel(
    const float* __restrict__ x, const float* __restrict__ h0,
    const float* __restrict__ Alog, float* __restrict__ out)
{
    const int d0 = blockIdx.x * 64;
    const int b0 = blockIdx.y * 16;
    const int tid = threadIdx.x;
    const int lane = tid & 31;
    const int w = tid >> 5;

    __shared__ float A2s[64][16];    // -exp(A_log)*log2(e)
    __shared__ float dt_s[16][64];
    __shared__ float y_s[16][64];
    __shared__ float Cs[16][16];
    __shared__ float SBCs[16];

    // A2s: 1024 floats = 256 float4 (one per thread)
    {
        int di = tid >> 2, n4 = (tid & 3) << 2;
        float4 al = *(const float4*)&Alog[(size_t)(d0 + di) * NN + n4];
        float4 o;
        o.x = -__expf(al.x) * 1.44269504f;
        o.y = -__expf(al.y) * 1.44269504f;
        o.z = -__expf(al.z) * 1.44269504f;
        o.w = -__expf(al.w) * 1.44269504f;
        *(float4*)&A2s[di][n4] = o;
    }
    // dt tile: 1024 floats = 256 float4
    {
        int b = tid >> 4, dq = (tid & 15) << 2;
        *(float4*)&dt_s[b][dq] =
            *(const float4*)&g_DT[(size_t)(b0 + b) * DD + d0 + dq];
    }
    // C, SBC
    {
        int b = tid >> 4, n = tid & 15;
        Cs[b][n] = g_T[(b0 + b) * JJ + RR + NN + n];
    }
    if (tid < 16) {
        float s = 0.f;
#pragma unroll
        for (int n = 0; n < NN; n++)
            s += g_T[(b0 + tid) * JJ + RR + n] * g_T[(b0 + tid) * JJ + RR + NN + n];
        SBCs[tid] = s;
    }
    __syncthreads();

    // Dual-stream coalesced h0 sweep. Lane l -> (d = dg*8 + l/4, n=(l&3)*4..+3).
    {
        const int l4 = lane >> 2;
        const int n4 = (lane & 3) << 2;
        const int bA = w * 2, bB = w * 2 + 1;

        const float* hpA = &h0[((size_t)(b0 + bA) * DD + d0 + l4) * NN + n4];
        const float* hpB = hpA + (size_t)DD * NN;

        const float4 cA = *(const float4*)&Cs[bA][n4];
        const float4 cB = *(const float4*)&Cs[bB][n4];

        float4 hA0 = __ldcs((const float4*)hpA);
        float4 hB0 = __ldcs((const float4*)hpB);
        float4 hA1 = __ldcs((const float4*)(hpA + 128));
        float4 hB1 = __ldcs((const float4*)(hpB + 128));

#pragma unroll
        for (int dg = 0; dg < 8; dg++) {
            const int dloc = dg * 8 + l4;
            const float4 a2 = *(const float4*)&A2s[dloc][n4];
            const float dtA = dt_s[bA][dloc];
            const float dtB = dt_s[bB][dloc];

            float pA = ex2f(a2.x * dtA) * hA0.x * cA.x;
            pA = fmaf(ex2f(a2.y * dtA) * hA0.y, cA.y, pA);
            pA = fmaf(ex2f(a2.z * dtA) * hA0.z, cA.z, pA);
            pA = fmaf(ex2f(a2.w * dtA) * hA0.w, cA.w, pA);

            float pB = ex2f(a2.x * dtB) * hB0.x * cB.x;
            pB = fmaf(ex2f(a2.y * dtB) * hB0.y, cB.y, pB);
            pB = fmaf(ex2f(a2.z * dtB) * hB0.z, cB.z, pB);
            pB = fmaf(ex2f(a2.w * dtB) * hB0.w, cB.w, pB);

            hA0 = hA1; hB0 = hB1;
            if (dg < 6) {
                hA1 = __ldcs((const float4*)(hpA + (size_t)(dg + 2) * 128));
                hB1 = __ldcs((const float4*)(hpB + (size_t)(dg + 2) * 128));
            }

            pA += __shfl_xor_sync(0xffffffffu, pA, 1);
            pA += __shfl_xor_sync(0xffffffffu, pA, 2);
            pB += __shfl_xor_sync(0xffffffffu, pB, 1);
            pB += __shfl_xor_sync(0xffffffffu, pB, 2);
            if ((lane & 3) == 0) {
                y_s[bA][dloc] = pA;
                y_s[bB][dloc] = pB;
            }
        }
    }
    __syncthreads();

    // Combine + coalesced stores: out = y + dt*x*SBC + x (256 float4s)
    {
        const int b = tid >> 4, dq = (tid & 15) << 2;
        const size_t g = (size_t)(b0 + b) * DD + d0 + dq;
        float4 xv = *(const float4*)&x[g];
        float4 dtv = *(const float4*)&dt_s[b][dq];
        float4 yv = *(const float4*)&y_s[b][dq];
        const float sbc = SBCs[b];
        float4 o;
        o.x = yv.x + fmaf(dtv.x * xv.x, sbc, xv.x);
        o.y = yv.y + fmaf(dtv.y * xv.y, sbc, xv.y);
        o.z = yv.z + fmaf(dtv.z * xv.z, sbc, xv.z);
        o.w = yv.w + fmaf(dtv.w * xv.w, sbc, xv.w);
        *(float4*)&out[g] = o;
    }
}

// ---------------------------------------------------------------------------
extern "C" void kernel_launch(void* const* d_in, const int* in_sizes, int n_in,
                              void* d_out, int out_size)
{
    const float* x    = (const float*)d_in[0];
    const float* h0   = (const float*)d_in[1];
    const float* Wx   = (const float*)d_in[2];
    const float* Wdt  = (const float*)d_in[3];
    const float* bdt  = (const float*)d_in[4];
    const float* Wbc  = (const float*)d_in[5];
    const float* Alog = (const float*)d_in[6];
    float* out = (float*)d_out;

    mamba_proj_kernel<<<dim3(2, 3, KSPLIT), 128>>>(x, Wx, Wbc, h0);
    mamba_reduce_kernel<<<(BB * JJ) / 256, 256>>>();
    mamba_dt_kernel<<<dim3(DD / 128, BB / 32), 256>>>(Wdt, bdt);
    mamba_scan_kernel<<<dim3(DD / 64, BB / 16), 256>>>(x, h0, Alog, out);
}

// round 10
// speedup vs baseline: 1.0894x; 1.0894x over previous
#include <cuda_runtime.h>

#define BB 256
#define DD 5120
#define NN 16
#define RR 160
#define JJ 192          // RR + 32 (B/C projections)
#define KSPLIT 80
#define KCH (DD / KSPLIT)   // 64
#define BK 16

// Scratch (device globals — no allocations allowed)
__device__ float g_P[KSPLIT * BB * JJ];   // split-K partials (15.7 MB)
__device__ float g_T[BB * JJ];            // reduced projections
__device__ float g_DT[BB * DD];           // dt (5.2 MB)

__device__ __forceinline__ float ex2f(float v) {
    float r;
    asm("ex2.approx.ftz.f32 %0, %1;" : "=f"(r) : "f"(v));
    return r;
}

typedef unsigned long long ull;

__device__ __forceinline__ ull fma2(ull a, ull b, ull c) {
    ull d;
    asm("fma.rn.f32x2 %0, %1, %2, %3;" : "=l"(d) : "l"(a), "l"(b), "l"(c));
    return d;
}
__device__ __forceinline__ float2 unpk(ull v) {
    float2 r;
    asm("mov.b64 {%0, %1}, %2;" : "=f"(r.x), "=f"(r.y) : "l"(v));
    return r;
}

// ---------------------------------------------------------------------------
// Kernel 1 (v4): split-K GEMM. P[ks] = x[:, k-chunk] @ [W_x_dt | W_BC]
// Tile 64(M) x 64(N), BK=16, double-buffered, 256 threads, micro 4M x 4N.
// Inner loop: 3 LDS + 8 FFMA2 per kk. ~40 regs, 25 KB smem -> 6 blocks/SM.
// Grid (4, 3, 80) = 960 blocks (~6.5/SM demand -> occ ~75%).
// ---------------------------------------------------------------------------
__global__ __launch_bounds__(256) void mamba_proj_kernel(
    const float* __restrict__ x, const float* __restrict__ Wx,
    const float* __restrict__ Wbc, const float* __restrict__ h0)
{
    __shared__ float2 As2[2][BK][66];   // [buf][k][m] duplicated, padded
    __shared__ float  Bs[2][BK][64];    // [buf][k][n]
    const int m0 = blockIdx.x * 64;
    const int n0 = blockIdx.y * 64;
    const int k0 = blockIdx.z * KCH;
    const int tid = threadIdx.x;
    const int tx = tid & 15, ty = tid >> 4;   // micro coords: n=tx*4, m=ty*4

    // ---- h0 L2 prefetch: 655360 lines of 128B over 960 blocks ----
    {
        const int bid = blockIdx.x + blockIdx.y * 4 + blockIdx.z * 12;  // 0..959
        const size_t total = (size_t)BB * DD * NN;
        size_t base = (size_t)bid * 683 * 32;
#pragma unroll
        for (int i = 0; i < 3; i++) {
            size_t off = base + ((size_t)(tid + i * 256)) * 32;
            if ((tid + i * 256) < 683 && off < total)
                asm volatile("prefetch.global.L2 [%0];" :: "l"(h0 + off) : "memory");
        }
    }

    // A loader: 1 float4/thread: m = tid>>2 (0..63), k4 = (tid&3)*4
    const int am = tid >> 2, ak = (tid & 3) << 2;
    // B loader: 1 float4/thread: k = tid>>4, n4 = (tid&15)*4
    const int bk_ = tid >> 4, bn = (tid & 15) << 2;

    // Branch-free W source (column j fixed per thread)
    const int j = n0 + bn;
    const float* bbase;
    size_t bstride;
    if (j < RR) { bbase = Wx + j;         bstride = RR; }
    else        { bbase = Wbc + (j - RR); bstride = 32; }

    const float* asrc = &x[(size_t)(m0 + am) * DD + k0 + ak];

    ull acc2[4][2] = {};

    // prologue: chunk 0
    float4 av = *(const float4*)asrc;
    float4 bv = *(const float4*)&bbase[(size_t)(k0 + bk_) * bstride];
    As2[0][ak + 0][am] = make_float2(av.x, av.x);
    As2[0][ak + 1][am] = make_float2(av.y, av.y);
    As2[0][ak + 2][am] = make_float2(av.z, av.z);
    As2[0][ak + 3][am] = make_float2(av.w, av.w);
    *(float4*)&Bs[0][bk_][bn] = bv;
    __syncthreads();

#pragma unroll
    for (int c = 0; c < KCH / BK; c++) {
        const int cur = c & 1;
        if (c + 1 < KCH / BK) {
            av = *(const float4*)(asrc + (c + 1) * BK);
            bv = *(const float4*)&bbase[(size_t)(k0 + (c + 1) * BK + bk_) * bstride];
        }
#pragma unroll
        for (int kk = 0; kk < BK; kk++) {
            ulonglong2 bq   = *(const ulonglong2*)&Bs[cur][kk][tx * 4];
            ulonglong2 aq01 = *(const ulonglong2*)&As2[cur][kk][ty * 4];
            ulonglong2 aq23 = *(const ulonglong2*)&As2[cur][kk][ty * 4 + 2];
            acc2[0][0] = fma2(aq01.x, bq.x, acc2[0][0]);
            acc2[0][1] = fma2(aq01.x, bq.y, acc2[0][1]);
            acc2[1][0] = fma2(aq01.y, bq.x, acc2[1][0]);
            acc2[1][1] = fma2(aq01.y, bq.y, acc2[1][1]);
            acc2[2][0] = fma2(aq23.x, bq.x, acc2[2][0]);
            acc2[2][1] = fma2(aq23.x, bq.y, acc2[2][1]);
            acc2[3][0] = fma2(aq23.y, bq.x, acc2[3][0]);
            acc2[3][1] = fma2(aq23.y, bq.y, acc2[3][1]);
        }
        if (c + 1 < KCH / BK) {
            const int nxt = cur ^ 1;
            __syncthreads();
            As2[nxt][ak + 0][am] = make_float2(av.x, av.x);
            As2[nxt][ak + 1][am] = make_float2(av.y, av.y);
            As2[nxt][ak + 2][am] = make_float2(av.z, av.z);
            As2[nxt][ak + 3][am] = make_float2(av.w, av.w);
            *(float4*)&Bs[nxt][bk_][bn] = bv;
            __syncthreads();
        }
    }

    float* dst = &g_P[(size_t)blockIdx.z * (BB * JJ)];
#pragma unroll
    for (int i = 0; i < 4; i++) {
        float2 p0 = unpk(acc2[i][0]);
        float2 p1 = unpk(acc2[i][1]);
        *(float4*)&dst[(size_t)(m0 + ty * 4 + i) * JJ + n0 + tx * 4] =
            make_float4(p0.x, p0.y, p1.x, p1.y);
    }
}

// ---------------------------------------------------------------------------
// Kernel 1r: reduce split-K partials. One thread per float, grid 192.
// ---------------------------------------------------------------------------
__global__ __launch_bounds__(256) void mamba_reduce_kernel()
{
    const int idx = blockIdx.x * 256 + threadIdx.x;
    float s = 0.f;
#pragma unroll
    for (int ks = 0; ks < KSPLIT; ks++) s += g_P[ks * (BB * JJ) + idx];
    g_T[idx] = s;
}

// ---------------------------------------------------------------------------
// Kernel 2a: dt GEMM.  z = t @ W_dt + b_dt ; dt = softplus(z) -> g_DT
// (R8 version, unchanged)
// ---------------------------------------------------------------------------
__global__ __launch_bounds__(256) void mamba_dt_kernel(
    const float* __restrict__ Wdt, const float* __restrict__ bdt)
{
    const int d0 = blockIdx.x * 128;
    const int b0 = blockIdx.y * 32;
    const int tid = threadIdx.x;
    const int tdx = tid & 31;     // d lane (4 consecutive d)
    const int tby = tid >> 5;     // warp id = b group (4 b per warp)

    __shared__ float2 Ts2[32][160];  // t tile, duplicated (41 KB)
    __shared__ float  Ws[16][128];   // W_dt chunk
    __shared__ float  bds[128];

    for (int v = tid; v < 1280; v += 256) {
        int b = v / 40, r4 = (v - b * 40) * 4;
        float4 t4 = *(const float4*)&g_T[(b0 + b) * JJ + r4];
        Ts2[b][r4 + 0] = make_float2(t4.x, t4.x);
        Ts2[b][r4 + 1] = make_float2(t4.y, t4.y);
        Ts2[b][r4 + 2] = make_float2(t4.z, t4.z);
        Ts2[b][r4 + 3] = make_float2(t4.w, t4.w);
    }
    if (tid < 128) bds[tid] = bdt[d0 + tid];

    ull acc2[4][2] = {};
    const int wr = tid >> 4;          // 0..15
    const int wc = (tid & 15) << 3;   // 0..120
    for (int rc = 0; rc < RR; rc += 16) {
        const float* wsrc = &Wdt[(size_t)(rc + wr) * DD + d0 + wc];
        float4 w0 = *(const float4*)wsrc;
        float4 w1 = *(const float4*)(wsrc + 4);
        __syncthreads();
        *(float4*)&Ws[wr][wc] = w0;
        *(float4*)&Ws[wr][wc + 4] = w1;
        __syncthreads();
#pragma unroll
        for (int rr = 0; rr < 16; rr++) {
            ulonglong2 wq = *(const ulonglong2*)&Ws[rr][tdx * 4];
            ull a0 = *(const ull*)&Ts2[tby * 4 + 0][rc + rr];  // bcast LDS.64
            ull a1 = *(const ull*)&Ts2[tby * 4 + 1][rc + rr];
            ull a2 = *(const ull*)&Ts2[tby * 4 + 2][rc + rr];
            ull a3 = *(const ull*)&Ts2[tby * 4 + 3][rc + rr];
            acc2[0][0] = fma2(a0, wq.x, acc2[0][0]);
            acc2[0][1] = fma2(a0, wq.y, acc2[0][1]);
            acc2[1][0] = fma2(a1, wq.x, acc2[1][0]);
            acc2[1][1] = fma2(a1, wq.y, acc2[1][1]);
            acc2[2][0] = fma2(a2, wq.x, acc2[2][0]);
            acc2[2][1] = fma2(a2, wq.y, acc2[2][1]);
            acc2[3][0] = fma2(a3, wq.x, acc2[3][0]);
            acc2[3][1] = fma2(a3, wq.y, acc2[3][1]);
        }
    }

    float4 bdv = *(const float4*)&bds[tdx * 4];
#pragma unroll
    for (int bi = 0; bi < 4; bi++) {
        const int bl = tby * 4 + bi;
        float2 p0 = unpk(acc2[bi][0]);
        float2 p1 = unpk(acc2[bi][1]);
        float z0 = p0.x + bdv.x, z1 = p0.y + bdv.y;
        float z2 = p1.x + bdv.z, z3 = p1.y + bdv.w;
        float4 dtv;
        dtv.x = fmaxf(z0, 0.f) + log1pf(__expf(-fabsf(z0)));
        dtv.y = fmaxf(z1, 0.f) + log1pf(__expf(-fabsf(z1)));
        dtv.z = fmaxf(z2, 0.f) + log1pf(__expf(-fabsf(z2)));
        dtv.w = fmaxf(z3, 0.f) + log1pf(__expf(-fabsf(z3)));
        *(float4*)&g_DT[(size_t)(b0 + bl) * DD + d0 + tdx * 4] = dtv;
    }
}

// ---------------------------------------------------------------------------
// Kernel 2b: h0 stream (R8 version, unchanged: d-tile 128, grid 640,
// dual-stream depth-2 prefetch, 4 KB streams).
// ---------------------------------------------------------------------------
__global__ __launch_bounds__(256) void mamba_scan_kernel(
    const float* __restrict__ x, const float* __restrict__ h0,
    const float* __restrict__ Alog, float* __restrict__ out)
{
    const int d0 = blockIdx.x * 128;
    const int b0 = blockIdx.y * 16;
    const int tid = threadIdx.x;
    const int lane = tid & 31;
    const int w = tid >> 5;

    __shared__ float A2s[128][16];   // -exp(A_log)*log2(e)
    __shared__ float dt_s[16][128];
    __shared__ float y_s[16][128];
    __shared__ float Cs[16][16];
    __shared__ float SBCs[16];

#pragma unroll
    for (int v = tid; v < 512; v += 256) {
        int di = v >> 2, n4 = (v & 3) << 2;
        float4 al = *(const float4*)&Alog[(size_t)(d0 + di) * NN + n4];
        float4 o;
        o.x = -__expf(al.x) * 1.44269504f;
        o.y = -__expf(al.y) * 1.44269504f;
        o.z = -__expf(al.z) * 1.44269504f;
        o.w = -__expf(al.w) * 1.44269504f;
        *(float4*)&A2s[di][n4] = o;
    }
#pragma unroll
    for (int v = tid; v < 512; v += 256) {
        int b = v >> 5, dq = (v & 31) << 2;
        *(float4*)&dt_s[b][dq] =
            *(const float4*)&g_DT[(size_t)(b0 + b) * DD + d0 + dq];
    }
    {
        int b = tid >> 4, n = tid & 15;
        Cs[b][n] = g_T[(b0 + b) * JJ + RR + NN + n];
    }
    if (tid < 16) {
        float s = 0.f;
#pragma unroll
        for (int n = 0; n < NN; n++)
            s += g_T[(b0 + tid) * JJ + RR + n] * g_T[(b0 + tid) * JJ + RR + NN + n];
        SBCs[tid] = s;
    }
    __syncthreads();

    {
        const int l4 = lane >> 2;
        const int n4 = (lane & 3) << 2;
        const int bA = w * 2, bB = w * 2 + 1;

        const float* hpA = &h0[((size_t)(b0 + bA) * DD + d0 + l4) * NN + n4];
        const float* hpB = hpA + (size_t)DD * NN;

        const float4 cA = *(const float4*)&Cs[bA][n4];
        const float4 cB = *(const float4*)&Cs[bB][n4];

        float4 hA0 = __ldcs((const float4*)hpA);
        float4 hB0 = __ldcs((const float4*)hpB);
        float4 hA1 = __ldcs((const float4*)(hpA + 128));
        float4 hB1 = __ldcs((const float4*)(hpB + 128));

#pragma unroll
        for (int dg = 0; dg < 16; dg++) {
            const int dloc = dg * 8 + l4;
            const float4 a2 = *(const float4*)&A2s[dloc][n4];
            const float dtA = dt_s[bA][dloc];
            const float dtB = dt_s[bB][dloc];

            float pA = ex2f(a2.x * dtA) * hA0.x * cA.x;
            pA = fmaf(ex2f(a2.y * dtA) * hA0.y, cA.y, pA);
            pA = fmaf(ex2f(a2.z * dtA) * hA0.z, cA.z, pA);
            pA = fmaf(ex2f(a2.w * dtA) * hA0.w, cA.w, pA);

            float pB = ex2f(a2.x * dtB) * hB0.x * cB.x;
            pB = fmaf(ex2f(a2.y * dtB) * hB0.y, cB.y, pB);
            pB = fmaf(ex2f(a2.z * dtB) * hB0.z, cB.z, pB);
            pB = fmaf(ex2f(a2.w * dtB) * hB0.w, cB.w, pB);

            hA0 = hA1; hB0 = hB1;
            if (dg < 14) {
                hA1 = __ldcs((const float4*)(hpA + (size_t)(dg + 2) * 128));
                hB1 = __ldcs((const float4*)(hpB + (size_t)(dg + 2) * 128));
            }

            pA += __shfl_xor_sync(0xffffffffu, pA, 1);
            pA += __shfl_xor_sync(0xffffffffu, pA, 2);
            pB += __shfl_xor_sync(0xffffffffu, pB, 1);
            pB += __shfl_xor_sync(0xffffffffu, pB, 2);
            if ((lane & 3) == 0) {
                y_s[bA][dloc] = pA;
                y_s[bB][dloc] = pB;
            }
        }
    }
    __syncthreads();

#pragma unroll
    for (int v = tid; v < 512; v += 256) {
        const int b = v >> 5, dq = (v & 31) << 2;
        const size_t g = (size_t)(b0 + b) * DD + d0 + dq;
        float4 xv = *(const float4*)&x[g];
        float4 dtv = *(const float4*)&dt_s[b][dq];
        float4 yv = *(const float4*)&y_s[b][dq];
        const float sbc = SBCs[b];
        float4 o;
        o.x = yv.x + fmaf(dtv.x * xv.x, sbc, xv.x);
        o.y = yv.y + fmaf(dtv.y * xv.y, sbc, xv.y);
        o.z = yv.z + fmaf(dtv.z * xv.z, sbc, xv.z);
        o.w = yv.w + fmaf(dtv.w * xv.w, sbc, xv.w);
        *(float4*)&out[g] = o;
    }
}

// ---------------------------------------------------------------------------
extern "C" void kernel_launch(void* const* d_in, const int* in_sizes, int n_in,
                              void* d_out, int out_size)
{
    const float* x    = (const float*)d_in[0];
    const float* h0   = (const float*)d_in[1];
    const float* Wx   = (const float*)d_in[2];
    const float* Wdt  = (const float*)d_in[3];
    const float* bdt  = (const float*)d_in[4];
    const float* Wbc  = (const float*)d_in[5];
    const float* Alog = (const float*)d_in[6];
    float* out = (float*)d_out;

    mamba_proj_kernel<<<dim3(4, 3, KSPLIT), 256>>>(x, Wx, Wbc, h0);
    mamba_reduce_kernel<<<(BB * JJ) / 256, 256>>>();
    mamba_dt_kernel<<<dim3(DD / 128, BB / 32), 256>>>(Wdt, bdt);
    mamba_scan_kernel<<<dim3(DD / 128, BB / 16), 256>>>(x, h0, Alog, out);
}

// round 12
// speedup vs baseline: 1.2025x; 1.1038x over previous
#include <cuda_runtime.h>
#include <cuda_bf16.h>
#include <mma.h>
#include <cstdint>

using namespace nvcuda;

#define BB 256
#define DD 5120
#define NN 16
#define RR 160
#define JJ 192          // RR + 32 (B/C projections)
#define KSPLIT 80
#define KCH 64          // DD / KSPLIT

// Scratch (device globals — no allocations allowed)
__device__ float g_P[KSPLIT * BB * JJ];   // split-K partials (15.7 MB)
__device__ float g_T[BB * JJ];            // reduced projections
__device__ float g_DT[BB * DD];           // dt (5.2 MB)

__device__ __forceinline__ float ex2f(float v) {
    float r;
    asm("ex2.approx.ftz.f32 %0, %1;" : "=f"(r) : "f"(v));
    return r;
}

typedef unsigned long long ull;

__device__ __forceinline__ ull fma2(ull a, ull b, ull c) {
    ull d;
    asm("fma.rn.f32x2 %0, %1, %2, %3;" : "=l"(d) : "l"(a), "l"(b), "l"(c));
    return d;
}
__device__ __forceinline__ float2 unpk(ull v) {
    float2 r;
    asm("mov.b64 {%0, %1}, %2;" : "=f"(r.x), "=f"(r.y) : "l"(v));
    return r;
}

// ---------------------------------------------------------------------------
// Kernel 1 (wmma): split-K GEMM via HMMA (plain sm_80 PTX; no 'a' features).
// P[ks] = x[:, ks*64 .. +64] @ [W_x_dt | W_BC], bf16 hi/lo 3-pass split.
// CTA: M=64, N=192, K=64 loaded to smem once. 256 threads = 8 warps:
// warp w -> (mrow = w&3)*16, (nhalf = w>>2)*96; 6 acc frags of 16x16.
// Grid (4, 80) = 320 CTAs.
// ---------------------------------------------------------------------------
// smem layout (bf16, ldm A=72, ldm B=200; all frag ptrs 32B-aligned)
#define PJ_AH 0
#define PJ_AL 9216
#define PJ_BH 18432
#define PJ_BL 44032
#define PJ_SMEM 69632

__global__ __launch_bounds__(256) void mamba_proj_wmma(
    const float* __restrict__ x, const float* __restrict__ Wx,
    const float* __restrict__ Wbc, const float* __restrict__ h0)
{
    extern __shared__ __align__(128) char smem[];
    __nv_bfloat16* Ah = (__nv_bfloat16*)(smem + PJ_AH);
    __nv_bfloat16* Al = (__nv_bfloat16*)(smem + PJ_AL);
    __nv_bfloat16* Bh = (__nv_bfloat16*)(smem + PJ_BH);
    __nv_bfloat16* Bl = (__nv_bfloat16*)(smem + PJ_BL);
    const int tid = threadIdx.x;
    const int m0 = blockIdx.x * 64;
    const int ks = blockIdx.y;
    const int k0 = ks * KCH;

    // h0 L2 prefetch: 655360 lines over 320 CTAs = 2048/CTA, 8/thread
    {
        const int bid = blockIdx.x + blockIdx.y * 4;   // 0..319
        const size_t total = (size_t)BB * DD * NN;
        size_t base = (size_t)bid * 2048 * 32;
#pragma unroll
        for (int i = 0; i < 8; i++) {
            size_t off = base + (size_t)(tid + i * 256) * 32;
            if (off < total)
                asm volatile("prefetch.global.L2 [%0];" :: "l"(h0 + off) : "memory");
        }
    }

    union U4 { ull u; __nv_bfloat16 h[4]; };

    // ---- A: x[m0+m][k0+k] -> bf16 hi/lo, [64 m][72 ldm] ----
#pragma unroll
    for (int v = tid; v < 1024; v += 256) {
        const int m = v >> 4, k4 = (v & 15) << 2;
        float4 xv = *(const float4*)&x[(size_t)(m0 + m) * DD + k0 + k4];
        const float* xf = (const float*)&xv;
        U4 hi, lo;
#pragma unroll
        for (int q = 0; q < 4; q++) {
            __nv_bfloat16 h = __float2bfloat16(xf[q]);
            hi.h[q] = h;
            lo.h[q] = __float2bfloat16(xf[q] - __bfloat162float(h));
        }
        *(ull*)(Ah + m * 72 + k4) = hi.u;
        *(ull*)(Al + m * 72 + k4) = lo.u;
    }
    // ---- B: [64 k][200 ldm], cols 0..159 from Wx, 160..191 from Wbc ----
#pragma unroll
    for (int v = tid; v < 2560; v += 256) {
        const int k = v / 40, n4 = (v % 40) * 4;
        float4 wv = *(const float4*)&Wx[(size_t)(k0 + k) * RR + n4];
        const float* wf = (const float*)&wv;
        U4 hi, lo;
#pragma unroll
        for (int q = 0; q < 4; q++) {
            __nv_bfloat16 h = __float2bfloat16(wf[q]);
            hi.h[q] = h;
            lo.h[q] = __float2bfloat16(wf[q] - __bfloat162float(h));
        }
        *(ull*)(Bh + k * 200 + n4) = hi.u;
        *(ull*)(Bl + k * 200 + n4) = lo.u;
    }
#pragma unroll
    for (int v = tid; v < 512; v += 256) {
        const int k = v >> 3, n4 = 160 + (v & 7) * 4;
        float4 wv = *(const float4*)&Wbc[(size_t)(k0 + k) * 32 + (n4 - 160)];
        const float* wf = (const float*)&wv;
        U4 hi, lo;
#pragma unroll
        for (int q = 0; q < 4; q++) {
            __nv_bfloat16 h = __float2bfloat16(wf[q]);
            hi.h[q] = h;
            lo.h[q] = __float2bfloat16(wf[q] - __bfloat162float(h));
        }
        *(ull*)(Bh + k * 200 + n4) = hi.u;
        *(ull*)(Bl + k * 200 + n4) = lo.u;
    }
    __syncthreads();

    // ---- wmma: 4 k-steps x 6 n-frags x 3 passes ----
    const int w = tid >> 5;
    const int mrow = w & 3;          // 0..3  -> m = mrow*16
    const int nh = w >> 2;           // 0..1  -> n base = nh*96

    wmma::fragment<wmma::accumulator, 16, 16, 16, float> acc[6];
#pragma unroll
    for (int j = 0; j < 6; j++) wmma::fill_fragment(acc[j], 0.0f);

#pragma unroll
    for (int kc = 0; kc < 4; kc++) {
        wmma::fragment<wmma::matrix_a, 16, 16, 16, __nv_bfloat16, wmma::row_major> a_h, a_l;
        wmma::load_matrix_sync(a_h, Ah + mrow * 16 * 72 + kc * 16, 72);
        wmma::load_matrix_sync(a_l, Al + mrow * 16 * 72 + kc * 16, 72);
#pragma unroll
        for (int j = 0; j < 6; j++) {
            const int n = nh * 96 + j * 16;
            wmma::fragment<wmma::matrix_b, 16, 16, 16, __nv_bfloat16, wmma::row_major> b_h, b_l;
            wmma::load_matrix_sync(b_h, Bh + kc * 16 * 200 + n, 200);
            wmma::load_matrix_sync(b_l, Bl + kc * 16 * 200 + n, 200);
            wmma::mma_sync(acc[j], a_h, b_h, acc[j]);
            wmma::mma_sync(acc[j], a_h, b_l, acc[j]);
            wmma::mma_sync(acc[j], a_l, b_h, acc[j]);
        }
    }

    // ---- store partials (fp32) straight to g_P ----
    float* dst = &g_P[(size_t)ks * (BB * JJ) + (size_t)(m0 + mrow * 16) * JJ + nh * 96];
#pragma unroll
    for (int j = 0; j < 6; j++)
        wmma::store_matrix_sync(dst + j * 16, acc[j], JJ, wmma::mem_row_major);
}

// ---------------------------------------------------------------------------
// Kernel 1r: reduce split-K partials. One thread per float, grid 192.
// ---------------------------------------------------------------------------
__global__ __launch_bounds__(256) void mamba_reduce_kernel()
{
    const int idx = blockIdx.x * 256 + threadIdx.x;
    float s = 0.f;
#pragma unroll
    for (int ks = 0; ks < KSPLIT; ks++) s += g_P[ks * (BB * JJ) + idx];
    g_T[idx] = s;
}

// ---------------------------------------------------------------------------
// Kernel 2a: dt GEMM (R8 version, unchanged).
// ---------------------------------------------------------------------------
__global__ __launch_bounds__(256) void mamba_dt_kernel(
    const float* __restrict__ Wdt, const float* __restrict__ bdt)
{
    const int d0 = blockIdx.x * 128;
    const int b0 = blockIdx.y * 32;
    const int tid = threadIdx.x;
    const int tdx = tid & 31;
    const int tby = tid >> 5;

    __shared__ float2 Ts2[32][160];
    __shared__ float  Ws[16][128];
    __shared__ float  bds[128];

    for (int v = tid; v < 1280; v += 256) {
        int b = v / 40, r4 = (v - b * 40) * 4;
        float4 t4 = *(const float4*)&g_T[(b0 + b) * JJ + r4];
        Ts2[b][r4 + 0] = make_float2(t4.x, t4.x);
        Ts2[b][r4 + 1] = make_float2(t4.y, t4.y);
        Ts2[b][r4 + 2] = make_float2(t4.z, t4.z);
        Ts2[b][r4 + 3] = make_float2(t4.w, t4.w);
    }
    if (tid < 128) bds[tid] = bdt[d0 + tid];

    ull acc2[4][2] = {};
    const int wr = tid >> 4;
    const int wc = (tid & 15) << 3;
    for (int rc = 0; rc < RR; rc += 16) {
        const float* wsrc = &Wdt[(size_t)(rc + wr) * DD + d0 + wc];
        float4 w0 = *(const float4*)wsrc;
        float4 w1 = *(const float4*)(wsrc + 4);
        __syncthreads();
        *(float4*)&Ws[wr][wc] = w0;
        *(float4*)&Ws[wr][wc + 4] = w1;
        __syncthreads();
#pragma unroll
        for (int rr = 0; rr < 16; rr++) {
            ulonglong2 wq = *(const ulonglong2*)&Ws[rr][tdx * 4];
            ull a0 = *(const ull*)&Ts2[tby * 4 + 0][rc + rr];
            ull a1 = *(const ull*)&Ts2[tby * 4 + 1][rc + rr];
            ull a2 = *(const ull*)&Ts2[tby * 4 + 2][rc + rr];
            ull a3 = *(const ull*)&Ts2[tby * 4 + 3][rc + rr];
            acc2[0][0] = fma2(a0, wq.x, acc2[0][0]);
            acc2[0][1] = fma2(a0, wq.y, acc2[0][1]);
            acc2[1][0] = fma2(a1, wq.x, acc2[1][0]);
            acc2[1][1] = fma2(a1, wq.y, acc2[1][1]);
            acc2[2][0] = fma2(a2, wq.x, acc2[2][0]);
            acc2[2][1] = fma2(a2, wq.y, acc2[2][1]);
            acc2[3][0] = fma2(a3, wq.x, acc2[3][0]);
            acc2[3][1] = fma2(a3, wq.y, acc2[3][1]);
        }
    }

    float4 bdv = *(const float4*)&bds[tdx * 4];
#pragma unroll
    for (int bi = 0; bi < 4; bi++) {
        const int bl = tby * 4 + bi;
        float2 p0 = unpk(acc2[bi][0]);
        float2 p1 = unpk(acc2[bi][1]);
        float z0 = p0.x + bdv.x, z1 = p0.y + bdv.y;
        float z2 = p1.x + bdv.z, z3 = p1.y + bdv.w;
        float4 dtv;
        dtv.x = fmaxf(z0, 0.f) + log1pf(__expf(-fabsf(z0)));
        dtv.y = fmaxf(z1, 0.f) + log1pf(__expf(-fabsf(z1)));
        dtv.z = fmaxf(z2, 0.f) + log1pf(__expf(-fabsf(z2)));
        dtv.w = fmaxf(z3, 0.f) + log1pf(__expf(-fabsf(z3)));
        *(float4*)&g_DT[(size_t)(b0 + bl) * DD + d0 + tdx * 4] = dtv;
    }
}

// ---------------------------------------------------------------------------
// Kernel 2b: h0 stream (R8 version, unchanged: proven 21.0 us).
// ---------------------------------------------------------------------------
__global__ __launch_bounds__(256) void mamba_scan_kernel(
    const float* __restrict__ x, const float* __restrict__ h0,
    const float* __restrict__ Alog, float* __restrict__ out)
{
    const int d0 = blockIdx.x * 128;
    const int b0 = blockIdx.y * 16;
    const int tid = threadIdx.x;
    const int lane = tid & 31;
    const int w = tid >> 5;

    __shared__ float A2s[128][16];
    __shared__ float dt_s[16][128];
    __shared__ float y_s[16][128];
    __shared__ float Cs[16][16];
    __shared__ float SBCs[16];

#pragma unroll
    for (int v = tid; v < 512; v += 256) {
        int di = v >> 2, n4 = (v & 3) << 2;
        float4 al = *(const float4*)&Alog[(size_t)(d0 + di) * NN + n4];
        float4 o;
        o.x = -__expf(al.x) * 1.44269504f;
        o.y = -__expf(al.y) * 1.44269504f;
        o.z = -__expf(al.z) * 1.44269504f;
        o.w = -__expf(al.w) * 1.44269504f;
        *(float4*)&A2s[di][n4] = o;
    }
#pragma unroll
    for (int v = tid; v < 512; v += 256) {
        int b = v >> 5, dq = (v & 31) << 2;
        *(float4*)&dt_s[b][dq] =
            *(const float4*)&g_DT[(size_t)(b0 + b) * DD + d0 + dq];
    }
    {
        int b = tid >> 4, n = tid & 15;
        Cs[b][n] = g_T[(b0 + b) * JJ + RR + NN + n];
    }
    if (tid < 16) {
        float s = 0.f;
#pragma unroll
        for (int n = 0; n < NN; n++)
            s += g_T[(b0 + tid) * JJ + RR + n] * g_T[(b0 + tid) * JJ + RR + NN + n];
        SBCs[tid] = s;
    }
    __syncthreads();

    {
        const int l4 = lane >> 2;
        const int n4 = (lane & 3) << 2;
        const int bA = w * 2, bB = w * 2 + 1;

        const float* hpA = &h0[((size_t)(b0 + bA) * DD + d0 + l4) * NN + n4];
        const float* hpB = hpA + (size_t)DD * NN;

        const float4 cA = *(const float4*)&Cs[bA][n4];
        const float4 cB = *(const float4*)&Cs[bB][n4];

        float4 hA0 = __ldcs((const float4*)hpA);
        float4 hB0 = __ldcs((const float4*)hpB);
        float4 hA1 = __ldcs((const float4*)(hpA + 128));
        float4 hB1 = __ldcs((const float4*)(hpB + 128));

#pragma unroll
        for (int dg = 0; dg < 16; dg++) {
            const int dloc = dg * 8 + l4;
            const float4 a2 = *(const float4*)&A2s[dloc][n4];
            const float dtA = dt_s[bA][dloc];
            const float dtB = dt_s[bB][dloc];

            float pA = ex2f(a2.x * dtA) * hA0.x * cA.x;
            pA = fmaf(ex2f(a2.y * dtA) * hA0.y, cA.y, pA);
            pA = fmaf(ex2f(a2.z * dtA) * hA0.z, cA.z, pA);
            pA = fmaf(ex2f(a2.w * dtA) * hA0.w, cA.w, pA);

            float pB = ex2f(a2.x * dtB) * hB0.x * cB.x;
            pB = fmaf(ex2f(a2.y * dtB) * hB0.y, cB.y, pB);
            pB = fmaf(ex2f(a2.z * dtB) * hB0.z, cB.z, pB);
            pB = fmaf(ex2f(a2.w * dtB) * hB0.w, cB.w, pB);

            hA0 = hA1; hB0 = hB1;
            if (dg < 14) {
                hA1 = __ldcs((const float4*)(hpA + (size_t)(dg + 2) * 128));
                hB1 = __ldcs((const float4*)(hpB + (size_t)(dg + 2) * 128));
            }

            pA += __shfl_xor_sync(0xffffffffu, pA, 1);
            pA += __shfl_xor_sync(0xffffffffu, pA, 2);
            pB += __shfl_xor_sync(0xffffffffu, pB, 1);
            pB += __shfl_xor_sync(0xffffffffu, pB, 2);
            if ((lane & 3) == 0) {
                y_s[bA][dloc] = pA;
                y_s[bB][dloc] = pB;
            }
        }
    }
    __syncthreads();

#pragma unroll
    for (int v = tid; v < 512; v += 256) {
        const int b = v >> 5, dq = (v & 31) << 2;
        const size_t g = (size_t)(b0 + b) * DD + d0 + dq;
        float4 xv = *(const float4*)&x[g];
        float4 dtv = *(const float4*)&dt_s[b][dq];
        float4 yv = *(const float4*)&y_s[b][dq];
        const float sbc = SBCs[b];
        float4 o;
        o.x = yv.x + fmaf(dtv.x * xv.x, sbc, xv.x);
        o.y = yv.y + fmaf(dtv.y * xv.y, sbc, xv.y);
        o.z = yv.z + fmaf(dtv.z * xv.z, sbc, xv.z);
        o.w = yv.w + fmaf(dtv.w * xv.w, sbc, xv.w);
        *(float4*)&out[g] = o;
    }
}

// ---------------------------------------------------------------------------
extern "C" void kernel_launch(void* const* d_in, const int* in_sizes, int n_in,
                              void* d_out, int out_size)
{
    const float* x    = (const float*)d_in[0];
    const float* h0   = (const float*)d_in[1];
    const float* Wx   = (const float*)d_in[2];
    const float* Wdt  = (const float*)d_in[3];
    const float* bdt  = (const float*)d_in[4];
    const float* Wbc  = (const float*)d_in[5];
    const float* Alog = (const float*)d_in[6];
    float* out = (float*)d_out;

    cudaFuncSetAttribute(mamba_proj_wmma,
                         cudaFuncAttributeMaxDynamicSharedMemorySize, PJ_SMEM);
    mamba_proj_wmma<<<dim3(4, KSPLIT), 256, PJ_SMEM>>>(x, Wx, Wbc, h0);
    mamba_reduce_kernel<<<(BB * JJ) / 256, 256>>>();
    mamba_dt_kernel<<<dim3(DD / 128, BB / 32), 256>>>(Wdt, bdt);
    mamba_scan_kernel<<<dim3(DD / 128, BB / 16), 256>>>(x, h0, Alog, out);
}

// round 13
// speedup vs baseline: 1.3710x; 1.1402x over previous
#include <cuda_runtime.h>
#include <cuda_bf16.h>
#include <mma.h>
#include <cstdint>

using namespace nvcuda;

#define BB 256
#define DD 5120
#define NN 16
#define RR 160
#define JJ 192          // RR + 32 (B/C projections)
#define KSPLIT 80
#define KCH 64          // DD / KSPLIT

// Scratch (device globals — no allocations allowed)
__device__ float g_P[KSPLIT * BB * JJ];   // split-K partials (15.7 MB)
__device__ float g_T[BB * JJ];            // reduced projections
__device__ float g_DT[BB * DD];           // dt (5.2 MB)

__device__ __forceinline__ float ex2f(float v) {
    float r;
    asm("ex2.approx.ftz.f32 %0, %1;" : "=f"(r) : "f"(v));
    return r;
}

typedef unsigned long long ull;

// ---------------------------------------------------------------------------
// Kernel 1 (wmma, unchanged from R12): split-K GEMM via HMMA.
// P[ks] = x[:, ks*64 .. +64] @ [W_x_dt | W_BC], bf16 hi/lo 3-pass split.
// Grid (4, 80) = 320 CTAs, 256 threads.
// ---------------------------------------------------------------------------
#define PJ_AH 0
#define PJ_AL 9216
#define PJ_BH 18432
#define PJ_BL 44032
#define PJ_SMEM 69632

__global__ __launch_bounds__(256) void mamba_proj_wmma(
    const float* __restrict__ x, const float* __restrict__ Wx,
    const float* __restrict__ Wbc, const float* __restrict__ h0)
{
    extern __shared__ __align__(128) char smem[];
    __nv_bfloat16* Ah = (__nv_bfloat16*)(smem + PJ_AH);
    __nv_bfloat16* Al = (__nv_bfloat16*)(smem + PJ_AL);
    __nv_bfloat16* Bh = (__nv_bfloat16*)(smem + PJ_BH);
    __nv_bfloat16* Bl = (__nv_bfloat16*)(smem + PJ_BL);
    const int tid = threadIdx.x;
    const int m0 = blockIdx.x * 64;
    const int ks = blockIdx.y;
    const int k0 = ks * KCH;

    // h0 L2 prefetch: 655360 lines over 320 CTAs = 2048/CTA, 8/thread
    {
        const int bid = blockIdx.x + blockIdx.y * 4;   // 0..319
        const size_t total = (size_t)BB * DD * NN;
        size_t base = (size_t)bid * 2048 * 32;
#pragma unroll
        for (int i = 0; i < 8; i++) {
            size_t off = base + (size_t)(tid + i * 256) * 32;
            if (off < total)
                asm volatile("prefetch.global.L2 [%0];" :: "l"(h0 + off) : "memory");
        }
    }

    union U4 { ull u; __nv_bfloat16 h[4]; };

    // A: x[m0+m][k0+k] -> bf16 hi/lo, [64 m][72 ldm]
#pragma unroll
    for (int v = tid; v < 1024; v += 256) {
        const int m = v >> 4, k4 = (v & 15) << 2;
        float4 xv = *(const float4*)&x[(size_t)(m0 + m) * DD + k0 + k4];
        const float* xf = (const float*)&xv;
        U4 hi, lo;
#pragma unroll
        for (int q = 0; q < 4; q++) {
            __nv_bfloat16 h = __float2bfloat16(xf[q]);
            hi.h[q] = h;
            lo.h[q] = __float2bfloat16(xf[q] - __bfloat162float(h));
        }
        *(ull*)(Ah + m * 72 + k4) = hi.u;
        *(ull*)(Al + m * 72 + k4) = lo.u;
    }
    // B: [64 k][200 ldm], cols 0..159 from Wx, 160..191 from Wbc
#pragma unroll
    for (int v = tid; v < 2560; v += 256) {
        const int k = v / 40, n4 = (v % 40) * 4;
        float4 wv = *(const float4*)&Wx[(size_t)(k0 + k) * RR + n4];
        const float* wf = (const float*)&wv;
        U4 hi, lo;
#pragma unroll
        for (int q = 0; q < 4; q++) {
            __nv_bfloat16 h = __float2bfloat16(wf[q]);
            hi.h[q] = h;
            lo.h[q] = __float2bfloat16(wf[q] - __bfloat162float(h));
        }
        *(ull*)(Bh + k * 200 + n4) = hi.u;
        *(ull*)(Bl + k * 200 + n4) = lo.u;
    }
#pragma unroll
    for (int v = tid; v < 512; v += 256) {
        const int k = v >> 3, n4 = 160 + (v & 7) * 4;
        float4 wv = *(const float4*)&Wbc[(size_t)(k0 + k) * 32 + (n4 - 160)];
        const float* wf = (const float*)&wv;
        U4 hi, lo;
#pragma unroll
        for (int q = 0; q < 4; q++) {
            __nv_bfloat16 h = __float2bfloat16(wf[q]);
            hi.h[q] = h;
            lo.h[q] = __float2bfloat16(wf[q] - __bfloat162float(h));
        }
        *(ull*)(Bh + k * 200 + n4) = hi.u;
        *(ull*)(Bl + k * 200 + n4) = lo.u;
    }
    __syncthreads();

    const int w = tid >> 5;
    const int mrow = w & 3;
    const int nh = w >> 2;

    wmma::fragment<wmma::accumulator, 16, 16, 16, float> acc[6];
#pragma unroll
    for (int j = 0; j < 6; j++) wmma::fill_fragment(acc[j], 0.0f);

#pragma unroll
    for (int kc = 0; kc < 4; kc++) {
        wmma::fragment<wmma::matrix_a, 16, 16, 16, __nv_bfloat16, wmma::row_major> a_h, a_l;
        wmma::load_matrix_sync(a_h, Ah + mrow * 16 * 72 + kc * 16, 72);
        wmma::load_matrix_sync(a_l, Al + mrow * 16 * 72 + kc * 16, 72);
#pragma unroll
        for (int j = 0; j < 6; j++) {
            const int n = nh * 96 + j * 16;
            wmma::fragment<wmma::matrix_b, 16, 16, 16, __nv_bfloat16, wmma::row_major> b_h, b_l;
            wmma::load_matrix_sync(b_h, Bh + kc * 16 * 200 + n, 200);
            wmma::load_matrix_sync(b_l, Bl + kc * 16 * 200 + n, 200);
            wmma::mma_sync(acc[j], a_h, b_h, acc[j]);
            wmma::mma_sync(acc[j], a_h, b_l, acc[j]);
            wmma::mma_sync(acc[j], a_l, b_h, acc[j]);
        }
    }

    float* dst = &g_P[(size_t)ks * (BB * JJ) + (size_t)(m0 + mrow * 16) * JJ + nh * 96];
#pragma unroll
    for (int j = 0; j < 6; j++)
        wmma::store_matrix_sync(dst + j * 16, acc[j], JJ, wmma::mem_row_major);
}

// ---------------------------------------------------------------------------
// Kernel 1r: reduce split-K partials. One thread per float, grid 192.
// ---------------------------------------------------------------------------
__global__ __launch_bounds__(256) void mamba_reduce_kernel()
{
    const int idx = blockIdx.x * 256 + threadIdx.x;
    float s = 0.f;
#pragma unroll
    for (int ks = 0; ks < KSPLIT; ks++) s += g_P[ks * (BB * JJ) + idx];
    g_T[idx] = s;
}

// ---------------------------------------------------------------------------
// Kernel 2a (wmma): dt GEMM. z = t @ W_dt + b_dt ; dt = softplus(z) -> g_DT
// CTA 64(b) x 64(d), K=160 in 5 chunks of 32. bf16 hi/lo 3-pass.
// 256 threads = 8 warps: warp w -> m = (w&3)*16, n = (w>>2)*32, 2 acc frags.
// Grid (80, 4) = 320 CTAs.
// ---------------------------------------------------------------------------
#define DT_AH 0                 // [64][160] bf16 hi : 20480 B
#define DT_AL 20480             // lo
#define DT_BH 40960             // [32][72] bf16 hi : 4608 B
#define DT_BL 45568             // lo
#define DT_SMEM 50176           // acc staging [64][64] fp32 = 16384 reuses A region

__global__ __launch_bounds__(256) void mamba_dt_wmma(
    const float* __restrict__ Wdt, const float* __restrict__ bdt)
{
    extern __shared__ __align__(128) char smem[];
    __nv_bfloat16* Ah = (__nv_bfloat16*)(smem + DT_AH);
    __nv_bfloat16* Al = (__nv_bfloat16*)(smem + DT_AL);
    __nv_bfloat16* Bh = (__nv_bfloat16*)(smem + DT_BH);
    __nv_bfloat16* Bl = (__nv_bfloat16*)(smem + DT_BL);
    const int tid = threadIdx.x;
    const int d0 = blockIdx.x * 64;
    const int b0 = blockIdx.y * 64;

    union U4 { ull u; __nv_bfloat16 h[4]; };

    // A: g_T[b0+m][r] (64 x 160) -> bf16 hi/lo, ldm 160
#pragma unroll
    for (int v = tid; v < 2560; v += 256) {
        const int m = v / 40, r4 = (v % 40) * 4;
        float4 t4 = *(const float4*)&g_T[(b0 + m) * JJ + r4];
        const float* tf = (const float*)&t4;
        U4 hi, lo;
#pragma unroll
        for (int q = 0; q < 4; q++) {
            __nv_bfloat16 h = __float2bfloat16(tf[q]);
            hi.h[q] = h;
            lo.h[q] = __float2bfloat16(tf[q] - __bfloat162float(h));
        }
        *(ull*)(Ah + m * 160 + r4) = hi.u;
        *(ull*)(Al + m * 160 + r4) = lo.u;
    }

    const int w = tid >> 5;
    const int mrow = w & 3;       // m = mrow*16
    const int nh = w >> 2;        // n = nh*32

    wmma::fragment<wmma::accumulator, 16, 16, 16, float> acc[2];
    wmma::fill_fragment(acc[0], 0.0f);
    wmma::fill_fragment(acc[1], 0.0f);

#pragma unroll
    for (int kc = 0; kc < 5; kc++) {      // chunks of K=32
        if (kc > 0) __syncthreads();      // prev-chunk mma readers done
        // B chunk: Wdt[(kc*32 + k)*DD + d0 + n], 32 x 64 -> hi/lo, ldm 72
#pragma unroll
        for (int v = tid; v < 512; v += 256) {
            const int k = v >> 4, n4 = (v & 15) << 2;
            float4 wv = *(const float4*)&Wdt[(size_t)(kc * 32 + k) * DD + d0 + n4];
            const float* wf = (const float*)&wv;
            U4 hi, lo;
#pragma unroll
            for (int q = 0; q < 4; q++) {
                __nv_bfloat16 h = __float2bfloat16(wf[q]);
                hi.h[q] = h;
                lo.h[q] = __float2bfloat16(wf[q] - __bfloat162float(h));
            }
            *(ull*)(Bh + k * 72 + n4) = hi.u;
            *(ull*)(Bl + k * 72 + n4) = lo.u;
        }
        __syncthreads();
#pragma unroll
        for (int kk = 0; kk < 2; kk++) {
            wmma::fragment<wmma::matrix_a, 16, 16, 16, __nv_bfloat16, wmma::row_major> a_h, a_l;
            wmma::load_matrix_sync(a_h, Ah + mrow * 16 * 160 + kc * 32 + kk * 16, 160);
            wmma::load_matrix_sync(a_l, Al + mrow * 16 * 160 + kc * 32 + kk * 16, 160);
#pragma unroll
            for (int j = 0; j < 2; j++) {
                const int n = nh * 32 + j * 16;
                wmma::fragment<wmma::matrix_b, 16, 16, 16, __nv_bfloat16, wmma::row_major> b_h, b_l;
                wmma::load_matrix_sync(b_h, Bh + kk * 16 * 72 + n, 72);
                wmma::load_matrix_sync(b_l, Bl + kk * 16 * 72 + n, 72);
                wmma::mma_sync(acc[j], a_h, b_h, acc[j]);
                wmma::mma_sync(acc[j], a_h, b_l, acc[j]);
                wmma::mma_sync(acc[j], a_l, b_h, acc[j]);
            }
        }
    }
    __syncthreads();   // all mma done before overwriting A region with staging

    // stage accumulators (fp32) into smem start, [64 m][64 n]
    float* st = (float*)smem;
    wmma::store_matrix_sync(st + (mrow * 16) * 64 + nh * 32,      acc[0], 64, wmma::mem_row_major);
    wmma::store_matrix_sync(st + (mrow * 16) * 64 + nh * 32 + 16, acc[1], 64, wmma::mem_row_major);
    __syncthreads();

    // epilogue: dt = softplus(z + b_dt) -> g_DT (coalesced float4)
#pragma unroll
    for (int v = tid; v < 1024; v += 256) {
        const int b = v >> 4, dq = (v & 15) << 2;
        float4 z4 = *(const float4*)&st[b * 64 + dq];
        float4 bd = *(const float4*)&bdt[d0 + dq];
        float4 dtv;
        float z0 = z4.x + bd.x, z1 = z4.y + bd.y, z2 = z4.z + bd.z, z3 = z4.w + bd.w;
        dtv.x = fmaxf(z0, 0.f) + log1pf(__expf(-fabsf(z0)));
        dtv.y = fmaxf(z1, 0.f) + log1pf(__expf(-fabsf(z1)));
        dtv.z = fmaxf(z2, 0.f) + log1pf(__expf(-fabsf(z2)));
        dtv.w = fmaxf(z3, 0.f) + log1pf(__expf(-fabsf(z3)));
        *(float4*)&g_DT[(size_t)(b0 + b) * DD + d0 + dq] = dtv;
    }
}

// ---------------------------------------------------------------------------
// Kernel 2b: h0 stream (R8 structure, prefetch depth 3: 6 LDG.128/warp in
// flight ≈ 25 KB/SM > the ~18 KB latency-BW product).
// ---------------------------------------------------------------------------
__global__ __launch_bounds__(256) void mamba_scan_kernel(
    const float* __restrict__ x, const float* __restrict__ h0,
    const float* __restrict__ Alog, float* __restrict__ out)
{
    const int d0 = blockIdx.x * 128;
    const int b0 = blockIdx.y * 16;
    const int tid = threadIdx.x;
    const int lane = tid & 31;
    const int w = tid >> 5;

    __shared__ float A2s[128][16];
    __shared__ float dt_s[16][128];
    __shared__ float y_s[16][128];
    __shared__ float Cs[16][16];
    __shared__ float SBCs[16];

#pragma unroll
    for (int v = tid; v < 512; v += 256) {
        int di = v >> 2, n4 = (v & 3) << 2;
        float4 al = *(const float4*)&Alog[(size_t)(d0 + di) * NN + n4];
        float4 o;
        o.x = -__expf(al.x) * 1.44269504f;
        o.y = -__expf(al.y) * 1.44269504f;
        o.z = -__expf(al.z) * 1.44269504f;
        o.w = -__expf(al.w) * 1.44269504f;
        *(float4*)&A2s[di][n4] = o;
    }
#pragma unroll
    for (int v = tid; v < 512; v += 256) {
        int b = v >> 5, dq = (v & 31) << 2;
        *(float4*)&dt_s[b][dq] =
            *(const float4*)&g_DT[(size_t)(b0 + b) * DD + d0 + dq];
    }
    {
        int b = tid >> 4, n = tid & 15;
        Cs[b][n] = g_T[(b0 + b) * JJ + RR + NN + n];
    }
    if (tid < 16) {
        float s = 0.f;
#pragma unroll
        for (int n = 0; n < NN; n++)
            s += g_T[(b0 + tid) * JJ + RR + n] * g_T[(b0 + tid) * JJ + RR + NN + n];
        SBCs[tid] = s;
    }
    __syncthreads();

    {
        const int l4 = lane >> 2;
        const int n4 = (lane & 3) << 2;
        const int bA = w * 2, bB = w * 2 + 1;

        const float* hpA = &h0[((size_t)(b0 + bA) * DD + d0 + l4) * NN + n4];
        const float* hpB = hpA + (size_t)DD * NN;

        const float4 cA = *(const float4*)&Cs[bA][n4];
        const float4 cB = *(const float4*)&Cs[bB][n4];

        float4 hA0 = __ldcs((const float4*)hpA);
        float4 hB0 = __ldcs((const float4*)hpB);
        float4 hA1 = __ldcs((const float4*)(hpA + 128));
        float4 hB1 = __ldcs((const float4*)(hpB + 128));
        float4 hA2 = __ldcs((const float4*)(hpA + 256));
        float4 hB2 = __ldcs((const float4*)(hpB + 256));

#pragma unroll
        for (int dg = 0; dg < 16; dg++) {
            const int dloc = dg * 8 + l4;
            const float4 a2 = *(const float4*)&A2s[dloc][n4];
            const float dtA = dt_s[bA][dloc];
            const float dtB = dt_s[bB][dloc];

            float pA = ex2f(a2.x * dtA) * hA0.x * cA.x;
            pA = fmaf(ex2f(a2.y * dtA) * hA0.y, cA.y, pA);
            pA = fmaf(ex2f(a2.z * dtA) * hA0.z, cA.z, pA);
            pA = fmaf(ex2f(a2.w * dtA) * hA0.w, cA.w, pA);

            float pB = ex2f(a2.x * dtB) * hB0.x * cB.x;
            pB = fmaf(ex2f(a2.y * dtB) * hB0.y, cB.y, pB);
            pB = fmaf(ex2f(a2.z * dtB) * hB0.z, cB.z, pB);
            pB = fmaf(ex2f(a2.w * dtB) * hB0.w, cB.w, pB);

            hA0 = hA1; hB0 = hB1;
            hA1 = hA2; hB1 = hB2;
            if (dg < 13) {
                hA2 = __ldcs((const float4*)(hpA + (size_t)(dg + 3) * 128));
                hB2 = __ldcs((const float4*)(hpB + (size_t)(dg + 3) * 128));
            }

            pA += __shfl_xor_sync(0xffffffffu, pA, 1);
            pA += __shfl_xor_sync(0xffffffffu, pA, 2);
            pB += __shfl_xor_sync(0xffffffffu, pB, 1);
            pB += __shfl_xor_sync(0xffffffffu, pB, 2);
            if ((lane & 3) == 0) {
                y_s[bA][dloc] = pA;
                y_s[bB][dloc] = pB;
            }
        }
    }
    __syncthreads();

#pragma unroll
    for (int v = tid; v < 512; v += 256) {
        const int b = v >> 5, dq = (v & 31) << 2;
        const size_t g = (size_t)(b0 + b) * DD + d0 + dq;
        float4 xv = *(const float4*)&x[g];
        float4 dtv = *(const float4*)&dt_s[b][dq];
        float4 yv = *(const float4*)&y_s[b][dq];
        const float sbc = SBCs[b];
        float4 o;
        o.x = yv.x + fmaf(dtv.x * xv.x, sbc, xv.x);
        o.y = yv.y + fmaf(dtv.y * xv.y, sbc, xv.y);
        o.z = yv.z + fmaf(dtv.z * xv.z, sbc, xv.z);
        o.w = yv.w + fmaf(dtv.w * xv.w, sbc, xv.w);
        *(float4*)&out[g] = o;
    }
}

// ---------------------------------------------------------------------------
extern "C" void kernel_launch(void* const* d_in, const int* in_sizes, int n_in,
                              void* d_out, int out_size)
{
    const float* x    = (const float*)d_in[0];
    const float* h0   = (const float*)d_in[1];
    const float* Wx   = (const float*)d_in[2];
    const float* Wdt  = (const float*)d_in[3];
    const float* bdt  = (const float*)d_in[4];
    const float* Wbc  = (const float*)d_in[5];
    const float* Alog = (const float*)d_in[6];
    float* out = (float*)d_out;

    cudaFuncSetAttribute(mamba_proj_wmma,
                         cudaFuncAttributeMaxDynamicSharedMemorySize, PJ_SMEM);
    cudaFuncSetAttribute(mamba_dt_wmma,
                         cudaFuncAttributeMaxDynamicSharedMemorySize, DT_SMEM);
    mamba_proj_wmma<<<dim3(4, KSPLIT), 256, PJ_SMEM>>>(x, Wx, Wbc, h0);
    mamba_reduce_kernel<<<(BB * JJ) / 256, 256>>>();
    mamba_dt_wmma<<<dim3(DD / 64, BB / 64), 256, DT_SMEM>>>(Wdt, bdt);
    mamba_scan_kernel<<<dim3(DD / 128, BB / 16), 256>>>(x, h0, Alog, out);
}

// round 14
// speedup vs baseline: 1.4406x; 1.0507x over previous
#include <cuda_runtime.h>
#include <cuda_bf16.h>
#include <mma.h>
#include <cstdint>

using namespace nvcuda;

#define BB 256
#define DD 5120
#define NN 16
#define RR 160
#define JJ 192          // RR + 32 (B/C projections)
#define KSPLIT 80
#define KCH 64          // DD / KSPLIT

// Scratch (device globals — no allocations allowed)
__device__ float g_P[KSPLIT * BB * JJ];   // split-K partials (15.7 MB)
__device__ float g_T[BB * JJ];            // reduced projections
__device__ float g_DT[BB * DD];           // dt (5.2 MB)

__device__ __forceinline__ float ex2f(float v) {
    float r;
    asm("ex2.approx.ftz.f32 %0, %1;" : "=f"(r) : "f"(v));
    return r;
}

typedef unsigned long long ull;

// Packed hi/lo bf16 split of a float4 (F2FP.BF16X2 path, half the cvts)
__device__ __forceinline__ void cvt_hilo4(float4 f, ull& hi, ull& lo) {
    union { ull u; __nv_bfloat162 h2[2]; } H, L;
    H.h2[0] = __float22bfloat162_rn(make_float2(f.x, f.y));
    H.h2[1] = __float22bfloat162_rn(make_float2(f.z, f.w));
    float2 g01 = __bfloat1622float2(H.h2[0]);
    float2 g23 = __bfloat1622float2(H.h2[1]);
    L.h2[0] = __float22bfloat162_rn(make_float2(f.x - g01.x, f.y - g01.y));
    L.h2[1] = __float22bfloat162_rn(make_float2(f.z - g23.x, f.w - g23.y));
    hi = H.u; lo = L.u;
}

// ---------------------------------------------------------------------------
// Kernel 1 (wmma): split-K GEMM via HMMA, m-tile 32 for occupancy.
// P[ks] = x[:, ks*64 .. +64] @ [W_x_dt | W_BC], bf16 hi/lo 3-pass split.
// Grid (8, 80) = 640 CTAs, 256 threads, smem ~59 KB (3 resident/SM).
// Warp w: mrow = w&1 (m = mrow*16), nq = w>>1 (n = nq*48, 3 frags).
// ---------------------------------------------------------------------------
#define PJ_AH 0
#define PJ_AL 4608            // [32][72] bf16 = 4608 B each
#define PJ_BH 9216            // [64][200] bf16 = 25600 B each
#define PJ_BL 34816
#define PJ_SMEM 60416

__global__ __launch_bounds__(256) void mamba_proj_wmma(
    const float* __restrict__ x, const float* __restrict__ Wx,
    const float* __restrict__ Wbc, const float* __restrict__ h0)
{
    extern __shared__ __align__(128) char smem[];
    __nv_bfloat16* Ah = (__nv_bfloat16*)(smem + PJ_AH);
    __nv_bfloat16* Al = (__nv_bfloat16*)(smem + PJ_AL);
    __nv_bfloat16* Bh = (__nv_bfloat16*)(smem + PJ_BH);
    __nv_bfloat16* Bl = (__nv_bfloat16*)(smem + PJ_BL);
    const int tid = threadIdx.x;
    const int m0 = blockIdx.x * 32;
    const int ks = blockIdx.y;
    const int k0 = ks * KCH;

    // h0 L2 prefetch: 655360 lines over 640 CTAs = 1024/CTA, 4/thread
    {
        const int bid = blockIdx.x + blockIdx.y * 8;   // 0..639
        const size_t total = (size_t)BB * DD * NN;
        size_t base = (size_t)bid * 1024 * 32;
#pragma unroll
        for (int i = 0; i < 4; i++) {
            size_t off = base + (size_t)(tid + i * 256) * 32;
            if (off < total)
                asm volatile("prefetch.global.L2 [%0];" :: "l"(h0 + off) : "memory");
        }
    }

    // A: x[m0+m][k0+k] -> bf16 hi/lo, [32 m][72 ldm]  (512 float4, 2/thread)
#pragma unroll
    for (int v = tid; v < 512; v += 256) {
        const int m = v >> 4, k4 = (v & 15) << 2;
        float4 xv = *(const float4*)&x[(size_t)(m0 + m) * DD + k0 + k4];
        ull hi, lo;
        cvt_hilo4(xv, hi, lo);
        *(ull*)(Ah + m * 72 + k4) = hi;
        *(ull*)(Al + m * 72 + k4) = lo;
    }
    // B: [64 k][200 ldm], cols 0..159 from Wx, 160..191 from Wbc
#pragma unroll
    for (int v = tid; v < 2560; v += 256) {
        const int k = v / 40, n4 = (v % 40) * 4;
        float4 wv = *(const float4*)&Wx[(size_t)(k0 + k) * RR + n4];
        ull hi, lo;
        cvt_hilo4(wv, hi, lo);
        *(ull*)(Bh + k * 200 + n4) = hi;
        *(ull*)(Bl + k * 200 + n4) = lo;
    }
#pragma unroll
    for (int v = tid; v < 512; v += 256) {
        const int k = v >> 3, n4 = 160 + (v & 7) * 4;
        float4 wv = *(const float4*)&Wbc[(size_t)(k0 + k) * 32 + (n4 - 160)];
        ull hi, lo;
        cvt_hilo4(wv, hi, lo);
        *(ull*)(Bh + k * 200 + n4) = hi;
        *(ull*)(Bl + k * 200 + n4) = lo;
    }
    __syncthreads();

    const int w = tid >> 5;
    const int mrow = w & 1;       // m = mrow*16
    const int nq = w >> 1;        // n base = nq*48

    wmma::fragment<wmma::accumulator, 16, 16, 16, float> acc[3];
#pragma unroll
    for (int j = 0; j < 3; j++) wmma::fill_fragment(acc[j], 0.0f);

#pragma unroll
    for (int kc = 0; kc < 4; kc++) {
        wmma::fragment<wmma::matrix_a, 16, 16, 16, __nv_bfloat16, wmma::row_major> a_h, a_l;
        wmma::load_matrix_sync(a_h, Ah + mrow * 16 * 72 + kc * 16, 72);
        wmma::load_matrix_sync(a_l, Al + mrow * 16 * 72 + kc * 16, 72);
#pragma unroll
        for (int j = 0; j < 3; j++) {
            const int n = nq * 48 + j * 16;
            wmma::fragment<wmma::matrix_b, 16, 16, 16, __nv_bfloat16, wmma::row_major> b_h, b_l;
            wmma::load_matrix_sync(b_h, Bh + kc * 16 * 200 + n, 200);
            wmma::load_matrix_sync(b_l, Bl + kc * 16 * 200 + n, 200);
            wmma::mma_sync(acc[j], a_h, b_h, acc[j]);
            wmma::mma_sync(acc[j], a_h, b_l, acc[j]);
            wmma::mma_sync(acc[j], a_l, b_h, acc[j]);
        }
    }

    float* dst = &g_P[(size_t)ks * (BB * JJ) + (size_t)(m0 + mrow * 16) * JJ + nq * 48];
#pragma unroll
    for (int j = 0; j < 3; j++)
        wmma::store_matrix_sync(dst + j * 16, acc[j], JJ, wmma::mem_row_major);
}

// ---------------------------------------------------------------------------
// Kernel 1r: reduce split-K partials. One thread per float, grid 192.
// ---------------------------------------------------------------------------
__global__ __launch_bounds__(256) void mamba_reduce_kernel()
{
    const int idx = blockIdx.x * 256 + threadIdx.x;
    float s = 0.f;
#pragma unroll
    for (int ks = 0; ks < KSPLIT; ks++) s += g_P[ks * (BB * JJ) + idx];
    g_T[idx] = s;
}

// ---------------------------------------------------------------------------
// Kernel 2a (wmma): dt GEMM, b-tile 32 for occupancy.
// z = t @ W_dt + b_dt ; dt = softplus(z) -> g_DT
// CTA 32(b) x 64(d), K=160 in 5 chunks of 32. smem ~29 KB (7 resident/SM).
// Grid (80, 8) = 640 CTAs. Warp w: mrow = w&1, nq = w>>1 (1 acc frag).
// ---------------------------------------------------------------------------
#define DT_AH 0                 // [32][160] bf16 = 10240 B each
#define DT_AL 10240
#define DT_BH 20480             // [32][72] bf16 = 4608 B each
#define DT_BL 25088
#define DT_SMEM 29696           // staging [32][64] f32 = 8192 reuses A region

__global__ __launch_bounds__(256) void mamba_dt_wmma(
    const float* __restrict__ Wdt, const float* __restrict__ bdt)
{
    extern __shared__ __align__(128) char smem[];
    __nv_bfloat16* Ah = (__nv_bfloat16*)(smem + DT_AH);
    __nv_bfloat16* Al = (__nv_bfloat16*)(smem + DT_AL);
    __nv_bfloat16* Bh = (__nv_bfloat16*)(smem + DT_BH);
    __nv_bfloat16* Bl = (__nv_bfloat16*)(smem + DT_BL);
    const int tid = threadIdx.x;
    const int d0 = blockIdx.x * 64;
    const int b0 = blockIdx.y * 32;

    // A: g_T[b0+m][r] (32 x 160) -> bf16 hi/lo, ldm 160 (640 float4)
#pragma unroll
    for (int v = tid; v < 640; v += 256) {
        const int m = v / 20, r4 = (v % 20) * 8;   // two float4 per v? no:
        // 32*40 = 1280 quads... redo: use 1280 float4 over 256 threads = 5 iters
    }
    // (corrected loop below)
#pragma unroll
    for (int v = tid; v < 1280; v += 256) {
        const int m = v / 40, r4 = (v % 40) * 4;
        float4 t4 = *(const float4*)&g_T[(b0 + m) * JJ + r4];
        ull hi, lo;
        cvt_hilo4(t4, hi, lo);
        *(ull*)(Ah + m * 160 + r4) = hi;
        *(ull*)(Al + m * 160 + r4) = lo;
    }

    const int w = tid >> 5;
    const int mrow = w & 1;       // m = mrow*16
    const int nq = w >> 1;        // n = nq*16

    wmma::fragment<wmma::accumulator, 16, 16, 16, float> acc;
    wmma::fill_fragment(acc, 0.0f);

#pragma unroll
    for (int kc = 0; kc < 5; kc++) {      // chunks of K=32
        if (kc > 0) __syncthreads();      // prev-chunk mma readers done
        // B chunk: Wdt[(kc*32 + k)*DD + d0 + n], 32 x 64 -> hi/lo, ldm 72
#pragma unroll
        for (int v = tid; v < 512; v += 256) {
            const int k = v >> 4, n4 = (v & 15) << 2;
            float4 wv = *(const float4*)&Wdt[(size_t)(kc * 32 + k) * DD + d0 + n4];
            ull hi, lo;
            cvt_hilo4(wv, hi, lo);
            *(ull*)(Bh + k * 72 + n4) = hi;
            *(ull*)(Bl + k * 72 + n4) = lo;
        }
        __syncthreads();
#pragma unroll
        for (int kk = 0; kk < 2; kk++) {
            wmma::fragment<wmma::matrix_a, 16, 16, 16, __nv_bfloat16, wmma::row_major> a_h, a_l;
            wmma::load_matrix_sync(a_h, Ah + mrow * 16 * 160 + kc * 32 + kk * 16, 160);
            wmma::load_matrix_sync(a_l, Al + mrow * 16 * 160 + kc * 32 + kk * 16, 160);
            wmma::fragment<wmma::matrix_b, 16, 16, 16, __nv_bfloat16, wmma::row_major> b_h, b_l;
            wmma::load_matrix_sync(b_h, Bh + kk * 16 * 72 + nq * 16, 72);
            wmma::load_matrix_sync(b_l, Bl + kk * 16 * 72 + nq * 16, 72);
            wmma::mma_sync(acc, a_h, b_h, acc);
            wmma::mma_sync(acc, a_h, b_l, acc);
            wmma::mma_sync(acc, a_l, b_h, acc);
        }
    }
    __syncthreads();   // all mma done before overwriting A region with staging

    // stage accumulators (fp32) into smem start, [32 m][64 n]
    float* st = (float*)smem;
    wmma::store_matrix_sync(st + (mrow * 16) * 64 + nq * 16, acc, 64,
                            wmma::mem_row_major);
    __syncthreads();

    // epilogue: dt = softplus(z + b_dt) -> g_DT (512 float4, 2/thread)
#pragma unroll
    for (int v = tid; v < 512; v += 256) {
        const int b = v >> 4, dq = (v & 15) << 2;
        float4 z4 = *(const float4*)&st[b * 64 + dq];
        float4 bd = *(const float4*)&bdt[d0 + dq];
        float4 dtv;
        float z0 = z4.x + bd.x, z1 = z4.y + bd.y, z2 = z4.z + bd.z, z3 = z4.w + bd.w;
        dtv.x = fmaxf(z0, 0.f) + log1pf(__expf(-fabsf(z0)));
        dtv.y = fmaxf(z1, 0.f) + log1pf(__expf(-fabsf(z1)));
        dtv.z = fmaxf(z2, 0.f) + log1pf(__expf(-fabsf(z2)));
        dtv.w = fmaxf(z3, 0.f) + log1pf(__expf(-fabsf(z3)));
        *(float4*)&g_DT[(size_t)(b0 + b) * DD + d0 + dq] = dtv;
    }
}

// ---------------------------------------------------------------------------
// Kernel 2b: h0 stream (R13 version, unchanged).
// ---------------------------------------------------------------------------
__global__ __launch_bounds__(256) void mamba_scan_kernel(
    const float* __restrict__ x, const float* __restrict__ h0,
    const float* __restrict__ Alog, float* __restrict__ out)
{
    const int d0 = blockIdx.x * 128;
    const int b0 = blockIdx.y * 16;
    const int tid = threadIdx.x;
    const int lane = tid & 31;
    const int w = tid >> 5;

    __shared__ float A2s[128][16];
    __shared__ float dt_s[16][128];
    __shared__ float y_s[16][128];
    __shared__ float Cs[16][16];
    __shared__ float SBCs[16];

#pragma unroll
    for (int v = tid; v < 512; v += 256) {
        int di = v >> 2, n4 = (v & 3) << 2;
        float4 al = *(const float4*)&Alog[(size_t)(d0 + di) * NN + n4];
        float4 o;
        o.x = -__expf(al.x) * 1.44269504f;
        o.y = -__expf(al.y) * 1.44269504f;
        o.z = -__expf(al.z) * 1.44269504f;
        o.w = -__expf(al.w) * 1.44269504f;
        *(float4*)&A2s[di][n4] = o;
    }
#pragma unroll
    for (int v = tid; v < 512; v += 256) {
        int b = v >> 5, dq = (v & 31) << 2;
        *(float4*)&dt_s[b][dq] =
            *(const float4*)&g_DT[(size_t)(b0 + b) * DD + d0 + dq];
    }
    {
        int b = tid >> 4, n = tid & 15;
        Cs[b][n] = g_T[(b0 + b) * JJ + RR + NN + n];
    }
    if (tid < 16) {
        float s = 0.f;
#pragma unroll
        for (int n = 0; n < NN; n++)
            s += g_T[(b0 + tid) * JJ + RR + n] * g_T[(b0 + tid) * JJ + RR + NN + n];
        SBCs[tid] = s;
    }
    __syncthreads();

    {
        const int l4 = lane >> 2;
        const int n4 = (lane & 3) << 2;
        const int bA = w * 2, bB = w * 2 + 1;

        const float* hpA = &h0[((size_t)(b0 + bA) * DD + d0 + l4) * NN + n4];
        const float* hpB = hpA + (size_t)DD * NN;

        const float4 cA = *(const float4*)&Cs[bA][n4];
        const float4 cB = *(const float4*)&Cs[bB][n4];

        float4 hA0 = __ldcs((const float4*)hpA);
        float4 hB0 = __ldcs((const float4*)hpB);
        float4 hA1 = __ldcs((const float4*)(hpA + 128));
        float4 hB1 = __ldcs((const float4*)(hpB + 128));
        float4 hA2 = __ldcs((const float4*)(hpA + 256));
        float4 hB2 = __ldcs((const float4*)(hpB + 256));

#pragma unroll
        for (int dg = 0; dg < 16; dg++) {
            const int dloc = dg * 8 + l4;
            const float4 a2 = *(const float4*)&A2s[dloc][n4];
            const float dtA = dt_s[bA][dloc];
            const float dtB = dt_s[bB][dloc];

            float pA = ex2f(a2.x * dtA) * hA0.x * cA.x;
            pA = fmaf(ex2f(a2.y * dtA) * hA0.y, cA.y, pA);
            pA = fmaf(ex2f(a2.z * dtA) * hA0.z, cA.z, pA);
            pA = fmaf(ex2f(a2.w * dtA) * hA0.w, cA.w, pA);

            float pB = ex2f(a2.x * dtB) * hB0.x * cB.x;
            pB = fmaf(ex2f(a2.y * dtB) * hB0.y, cB.y, pB);
            pB = fmaf(ex2f(a2.z * dtB) * hB0.z, cB.z, pB);
            pB = fmaf(ex2f(a2.w * dtB) * hB0.w, cB.w, pB);

            hA0 = hA1; hB0 = hB1;
            hA1 = hA2; hB1 = hB2;
            if (dg < 13) {
                hA2 = __ldcs((const float4*)(hpA + (size_t)(dg + 3) * 128));
                hB2 = __ldcs((const float4*)(hpB + (size_t)(dg + 3) * 128));
            }

            pA += __shfl_xor_sync(0xffffffffu, pA, 1);
            pA += __shfl_xor_sync(0xffffffffu, pA, 2);
            pB += __shfl_xor_sync(0xffffffffu, pB, 1);
            pB += __shfl_xor_sync(0xffffffffu, pB, 2);
            if ((lane & 3) == 0) {
                y_s[bA][dloc] = pA;
                y_s[bB][dloc] = pB;
            }
        }
    }
    __syncthreads();

#pragma unroll
    for (int v = tid; v < 512; v += 256) {
        const int b = v >> 5, dq = (v & 31) << 2;
        const size_t g = (size_t)(b0 + b) * DD + d0 + dq;
        float4 xv = *(const float4*)&x[g];
        float4 dtv = *(const float4*)&dt_s[b][dq];
        float4 yv = *(const float4*)&y_s[b][dq];
        const float sbc = SBCs[b];
        float4 o;
        o.x = yv.x + fmaf(dtv.x * xv.x, sbc, xv.x);
        o.y = yv.y + fmaf(dtv.y * xv.y, sbc, xv.y);
        o.z = yv.z + fmaf(dtv.z * xv.z, sbc, xv.z);
        o.w = yv.w + fmaf(dtv.w * xv.w, sbc, xv.w);
        *(float4*)&out[g] = o;
    }
}

// ---------------------------------------------------------------------------
extern "C" void kernel_launch(void* const* d_in, const int* in_sizes, int n_in,
                              void* d_out, int out_size)
{
    const float* x    = (const float*)d_in[0];
    const float* h0   = (const float*)d_in[1];
    const float* Wx   = (const float*)d_in[2];
    const float* Wdt  = (const float*)d_in[3];
    const float* bdt  = (const float*)d_in[4];
    const float* Wbc  = (const float*)d_in[5];
    const float* Alog = (const float*)d_in[6];
    float* out = (float*)d_out;

    cudaFuncSetAttribute(mamba_proj_wmma,
                         cudaFuncAttributeMaxDynamicSharedMemorySize, PJ_SMEM);
    cudaFuncSetAttribute(mamba_dt_wmma,
                         cudaFuncAttributeMaxDynamicSharedMemorySize, DT_SMEM);
    mamba_proj_wmma<<<dim3(8, KSPLIT), 256, PJ_SMEM>>>(x, Wx, Wbc, h0);
    mamba_reduce_kernel<<<(BB * JJ) / 256, 256>>>();
    mamba_dt_wmma<<<dim3(DD / 64, BB / 32), 256, DT_SMEM>>>(Wdt, bdt);
    mamba_scan_kernel<<<dim3(DD / 128, BB / 16), 256>>>(x, h0, Alog, out);
}